// round 6
// baseline (speedup 1.0000x reference)
#include <cuda_runtime.h>
#include <math.h>
#include <stdint.h>

#define B_ 128
#define N_ 4096
#define H_ 128
#define P_ 128
#define NTILES 32
#define THREADS 384
#define NEGC (-10000.0f)

// padded row stride: 132 floats = 528 bytes (33*16B -> LDSM conflict-free)
#define LDSF 132
#define LDSB 528

// ---------------- smem layout (float offsets) ----------------
#define F_W     0                      // 128*132 = 16896 (scaled tf32 Wv)
#define F_V0    16896                  // 16896
#define F_V1    (F_V0 + 16896)         // 16896 (also Wq staging in setup)
#define F_LSM   (F_V1 + 16896)         // 4096 logits
#define F_QW    (F_LSM + 4096)         // 256 (float2 qwas[128])
#define F_WE    (F_QW + 256)           // 128
#define F_LGP   (F_WE + 128)           // 1024 (double-buffered 2 x 512)
#define F_BC    (F_LGP + 1024)         // 16
#define F_RED   (F_BC + 16)            // 16
#define F_SCL   (F_RED + 16)           // 8
#define F_QROW  (F_SCL + 8)            // 128
#define SMEM_FLOATS (F_QROW + 128)

// ---------------- helpers ----------------
__device__ __forceinline__ float f2tf(float x) {
    uint32_t r;
    asm("cvt.rna.tf32.f32 %0, %1;" : "=r"(r) : "f"(x));
    return __uint_as_float(r);
}

__device__ __forceinline__ void mma_tf32(float* d,
                                         uint32_t a0, uint32_t a1, uint32_t a2, uint32_t a3,
                                         uint32_t b0, uint32_t b1) {
    asm volatile(
        "mma.sync.aligned.m16n8k8.row.col.f32.tf32.tf32.f32 "
        "{%0,%1,%2,%3}, {%4,%5,%6,%7}, {%8,%9}, {%0,%1,%2,%3};"
        : "+f"(d[0]), "+f"(d[1]), "+f"(d[2]), "+f"(d[3])
        : "r"(a0), "r"(a1), "r"(a2), "r"(a3), "r"(b0), "r"(b1));
}

__device__ __forceinline__ void ldsm4(uint32_t* r, uint32_t addr) {
    asm volatile("ldmatrix.sync.aligned.m8n8.x4.shared.b16 {%0,%1,%2,%3}, [%4];"
                 : "=r"(r[0]), "=r"(r[1]), "=r"(r[2]), "=r"(r[3]) : "r"(addr));
}

__device__ __forceinline__ void cp16(uint32_t dst, const void* src) {
    asm volatile("cp.async.cg.shared.global [%0], [%1], 16;" :: "r"(dst), "l"(src));
}
__device__ __forceinline__ void cp_commit() { asm volatile("cp.async.commit_group;" ::); }
__device__ __forceinline__ void cp_wait0()  { asm volatile("cp.async.wait_group 0;" ::); }
__device__ __forceinline__ void cp_wait1()  { asm volatile("cp.async.wait_group 1;" ::); }

#define BAR_SYNC(id, cnt)   asm volatile("bar.sync %0, %1;"   :: "r"(id), "r"(cnt) : "memory")
#define BAR_ARRIVE(id, cnt) asm volatile("bar.arrive %0, %1;" :: "r"(id), "r"(cnt) : "memory")
#define MEMBAR_CTA()        asm volatile("membar.cta;" ::: "memory")

// ---------------------------------------------------------------------------
// One CTA per batch row. 384 threads:
//   warps 0-7  (GEMM): each owns a 64x32 block of the 128x128 projection
//                      -> 2 GEMM warps per SMSP for tensor-pipe saturation
//   warps 8-11 (helper): logits combine + online softmax + att update +
//                        cp.async V prefetch, overlapped with GEMM(t+1).
// ---------------------------------------------------------------------------
__global__ void __launch_bounds__(THREADS, 1)
main_kernel(const float* __restrict__ v,
            const float* __restrict__ q,
            const float* __restrict__ mask,
            const float* __restrict__ Wv,
            const float* __restrict__ bv,
            const float* __restrict__ gv,
            const float* __restrict__ Wq,
            const float* __restrict__ bq,
            const float* __restrict__ gq,
            const float* __restrict__ Wa,
            const float* __restrict__ ba,
            const float* __restrict__ ga,
            float* __restrict__ out_att,
            float* __restrict__ out_w) {
    const int b    = blockIdx.x;
    const int tid  = threadIdx.x;
    const int warp = tid >> 5;
    const int lane = tid & 31;

    extern __shared__ float sm[];
    const uint32_t sb = (uint32_t)__cvta_generic_to_shared(sm);
    float*  lsm  = sm + F_LSM;
    float2* qwas = (float2*)(sm + F_QW);
    float*  we   = sm + F_WE;
    float*  lgp  = sm + F_LGP;
    float*  bc   = sm + F_BC;
    float*  red  = sm + F_RED;
    float*  scl  = sm + F_SCL;
    float*  qrow = sm + F_QROW;

    const float* vsrc = v + (size_t)b * N_ * H_;

    // =================== setup (all 384 threads) ===================
    float s0 = 0.f;
    for (int i = tid; i < 4096; i += THREADS) {
        int row = i >> 5, c4 = i & 31;
        float4 w4 = __ldg((const float4*)Wq + i);
        *(float4*)(sm + F_V1 + row * LDSF + c4 * 4) = w4;
        float4 a = __ldg((const float4*)Wv + i);
        s0 += a.x * a.x + a.y * a.y + a.z * a.z + a.w * a.w;
    }
    const float wa_own = (tid < P_) ? __ldg(&Wa[tid]) : 0.f;
    float s2 = wa_own * wa_own;
    if (tid < 32) ((float4*)qrow)[tid] = __ldg((const float4*)(q + b * H_) + tid);
    #pragma unroll
    for (int o = 16; o; o >>= 1) {
        s0 += __shfl_xor_sync(0xFFFFFFFFu, s0, o);
        s2 += __shfl_xor_sync(0xFFFFFFFFu, s2, o);
    }
    if (lane == 0) { red[warp] = s0; red[12 + warp] = s2; } // 12 warps: red has 16 slots? need 24
    __syncthreads();
    if (tid == 0) {
        float a = 0.f, c = 0.f;
        #pragma unroll
        for (int i = 0; i < 12; i++) { a += red[i]; c += red[12 + i] * 0.f; }
        // (red only has 16 slots; recompute c safely below)
        #pragma unroll
        for (int i = 0; i < 4; i++) c += red[12 + i];
        scl[0] = gv[0] / sqrtf(a);
        scl[2] = ga[0] / sqrtf(c);
        scl[3] = ba[0];
    }
    __syncthreads();
    const float sv = scl[0], sa = scl[2];

    // stage W (scaled, tf32 rna-rounded)
    for (int i = tid; i < 4096; i += THREADS) {
        int p = i >> 5, c4 = i & 31;
        float4 a = __ldg((const float4*)Wv + i);
        a.x = f2tf(sv * a.x); a.y = f2tf(sv * a.y);
        a.z = f2tf(sv * a.z); a.w = f2tf(sv * a.w);
        *(float4*)(sm + F_W + p * LDSF + c4 * 4) = a;
    }

    // qproj + Wq norm from staged rows (threads 0-127 own one row each)
    float dotv = 0.f, s1 = 0.f;
    if (tid < P_) {
        const float* wr = sm + F_V1 + tid * LDSF;
        #pragma unroll 8
        for (int h = 0; h < H_; h++) {
            float w = wr[h];
            dotv += w * qrow[h];
            s1 += w * w;
        }
    }
    #pragma unroll
    for (int o = 16; o; o >>= 1) s1 += __shfl_xor_sync(0xFFFFFFFFu, s1, o);
    if (lane == 0 && warp < 4) red[warp] = s1;
    __syncthreads();
    if (tid == 0) scl[1] = gq[0] / sqrtf(red[0] + red[1] + red[2] + red[3]);
    __syncthreads();
    if (tid < P_) {
        float2 qv;
        qv.x = scl[1] * dotv + __ldg(&bq[tid]) + __ldg(&bv[tid]);
        qv.y = sa * wa_own;
        qwas[tid] = qv;
    }
    __syncthreads();   // everyone done with V1 (Wq staging)
    const float ba0 = scl[3];

    // =================== split: GEMM group / helper group ===================
    if (warp < 8) {
        // ---------------- GEMM group: warp owns 64 rows x 32 cols ----------------
        const int t4 = lane & 3;
        const int mi = warp & 1;    // row half (64 rows)
        const int ni = warp >> 1;   // col quarter (32 cols)
        const int j  = lane >> 3;
        int aoff[4], boff[2];
        #pragma unroll
        for (int m = 0; m < 4; m++) {
            int row = mi * 64 + m * 16 + ((j & 1) << 3) + (lane & 7);
            aoff[m] = row * LDSB + ((j >> 1) << 4);
        }
        #pragma unroll
        for (int p = 0; p < 2; p++) {
            int row = ni * 32 + p * 16 + ((j >> 1) << 3) + (lane & 7);
            boff[p] = (F_W * 4) + row * LDSB + ((j & 1) << 4);
        }

        float4 qw[4];
        #pragma unroll
        for (int n = 0; n < 4; n++)
            qw[n] = *(const float4*)&qwas[ni * 32 + n * 8 + 2 * t4];

        for (int t = 0; t < NTILES; t++) {
            BAR_SYNC(1, THREADS);                   // V(t) ready
            const uint32_t vb = sb + ((t & 1) ? F_V1 : F_V0) * 4;

            float acc[4][4][4];
            #pragma unroll
            for (int m = 0; m < 4; m++)
                #pragma unroll
                for (int n = 0; n < 4; n++)
                    #pragma unroll
                    for (int x = 0; x < 4; x++) acc[m][n][x] = 0.f;

            #pragma unroll
            for (int k = 0; k < 16; k++) {
                uint32_t a[4][4], bb[2][4];
                #pragma unroll
                for (int m = 0; m < 4; m++) ldsm4(a[m], vb + aoff[m] + 32 * k);
                #pragma unroll
                for (int p = 0; p < 2; p++) ldsm4(bb[p], sb + boff[p] + 32 * k);
                #pragma unroll
                for (int m = 0; m < 4; m++)
                    #pragma unroll
                    for (int n = 0; n < 4; n++)
                        mma_tf32(acc[m][n], a[m][0], a[m][1], a[m][2], a[m][3],
                                 bb[n >> 1][(n & 1) * 2], bb[n >> 1][(n & 1) * 2 + 1]);
            }

            // relu + wa dot -> row partials into lgp[t&1] (4 col-groups)
            float* lgpb = lgp + (t & 1) * 512;
            #pragma unroll
            for (int m = 0; m < 4; m++) {
                float pl0 = 0.f, pl1 = 0.f;
                #pragma unroll
                for (int n = 0; n < 4; n++) {
                    pl0 += fmaxf(acc[m][n][0] + qw[n].x, 0.f) * qw[n].y
                         + fmaxf(acc[m][n][1] + qw[n].z, 0.f) * qw[n].w;
                    pl1 += fmaxf(acc[m][n][2] + qw[n].x, 0.f) * qw[n].y
                         + fmaxf(acc[m][n][3] + qw[n].z, 0.f) * qw[n].w;
                }
                pl0 += __shfl_xor_sync(0xFFFFFFFFu, pl0, 1);
                pl0 += __shfl_xor_sync(0xFFFFFFFFu, pl0, 2);
                pl1 += __shfl_xor_sync(0xFFFFFFFFu, pl1, 1);
                pl1 += __shfl_xor_sync(0xFFFFFFFFu, pl1, 2);
                if (t4 == 0) {
                    const int gg = lane >> 2;
                    const int r0 = mi * 64 + m * 16 + gg;
                    lgpb[r0 * 4 + ni]       = pl0;
                    lgpb[(r0 + 8) * 4 + ni] = pl1;
                }
            }
            MEMBAR_CTA();
            BAR_ARRIVE(2, THREADS);                 // lgp(t) ready
        }
    } else {
        // ---------------- helper group ----------------
        const int ht = tid - 256;     // 0..127, owns column ht
        const int hw = warp - 8;      // 0..3

        // prefetch V0, V1
        for (int i = ht; i < 4096; i += 128) {
            int row = i >> 5, c4 = i & 31;
            cp16(sb + (F_V0 + row * LDSF) * 4 + c4 * 16, vsrc + row * H_ + c4 * 4);
        }
        cp_commit();
        for (int i = ht; i < 4096; i += 128) {
            int row = i >> 5, c4 = i & 31;
            cp16(sb + (F_V1 + row * LDSF) * 4 + c4 * 16,
                 vsrc + (size_t)(128 + row) * H_ + c4 * 4);
        }
        cp_commit();
        cp_wait1();                                  // V0 done
        MEMBAR_CTA();
        BAR_ARRIVE(1, THREADS);                      // V(0) ready

        float M = -INFINITY, S = 0.f, attp = 0.f;

        for (int t = 0; t < NTILES; t++) {
            const float mkv = __ldg(&mask[(size_t)b * N_ + t * 128 + ht]);
            BAR_SYNC(2, THREADS);                    // lgp(t) ready
            cp_wait0();                              // V(t+1) complete
            MEMBAR_CTA();
            if (t < NTILES - 1) BAR_ARRIVE(1, THREADS);  // release GEMM(t+1)

            // combine 4 partials + mask -> logit
            const float4 lp = *(const float4*)&lgp[(t & 1) * 512 + ht * 4];
            float l = (lp.x + lp.y) + (lp.z + lp.w) + ba0 + (1.f - mkv) * NEGC;
            lsm[t * 128 + ht] = l;

            float x = l;
            #pragma unroll
            for (int o = 16; o; o >>= 1) x = fmaxf(x, __shfl_xor_sync(0xFFFFFFFFu, x, o));
            if (lane == 0) bc[hw] = x;
            BAR_SYNC(3, 128);
            float Mn = fmaxf(M, fmaxf(fmaxf(bc[0], bc[1]), fmaxf(bc[2], bc[3])));
            float r  = __expf(M - Mn);
            float e  = __expf(l - Mn);
            we[ht] = e;
            #pragma unroll
            for (int o = 16; o; o >>= 1) e += __shfl_xor_sync(0xFFFFFFFFu, e, o);
            if (lane == 0) bc[8 + hw] = e;
            BAR_SYNC(3, 128);                        // we[] + sums visible
            S = S * r + (bc[8] + bc[9] + bc[10] + bc[11]);
            M = Mn;

            // att update from V(t) (raw fp32 in smem)
            const float* Vg = sm + ((t & 1) ? F_V1 : F_V0);
            float a0 = 0.f, a1 = 0.f, a2 = 0.f, a3 = 0.f;
            #pragma unroll 8
            for (int row = 0; row < 128; row += 4) {
                a0 += we[row]     * Vg[row * LDSF + ht];
                a1 += we[row + 1] * Vg[(row + 1) * LDSF + ht];
                a2 += we[row + 2] * Vg[(row + 2) * LDSF + ht];
                a3 += we[row + 3] * Vg[(row + 3) * LDSF + ht];
            }
            attp = attp * r + ((a0 + a1) + (a2 + a3));
            BAR_SYNC(3, 128);                        // att reads done

            // prefetch V(t+2) into buf(t&1)
            if (t + 2 < NTILES) {
                const float* src = vsrc + (size_t)(t + 2) * 128 * H_;
                const uint32_t dstb = sb + ((t & 1) ? F_V1 : F_V0) * 4;
                for (int i = ht; i < 4096; i += 128) {
                    int row = i >> 5, c4 = i & 31;
                    cp16(dstb + (row * LDSF) * 4 + c4 * 16, src + row * H_ + c4 * 4);
                }
            }
            cp_commit();
        }

        if (ht == 0) { red[0] = M; red[1] = 1.f / S; }
        out_att[b * H_ + ht] = attp / S;
    }

    // =================== finals (all 384) ===================
    __syncthreads();
    const float Mf = red[0], invS = red[1];
    #pragma unroll 4
    for (int n = tid; n < N_; n += THREADS) {
        out_w[(size_t)b * N_ + n] = __expf(lsm[n] - Mf) * invS;
    }
}

// ---------------------------------------------------------------------------
extern "C" void kernel_launch(void* const* d_in, const int* in_sizes, int n_in,
                              void* d_out, int out_size) {
    const float* v    = (const float*)d_in[0];
    const float* q    = (const float*)d_in[1];
    const float* mask = (const float*)d_in[2];
    const float* Wv   = (const float*)d_in[3];
    const float* bv   = (const float*)d_in[4];
    const float* gv   = (const float*)d_in[5];
    const float* Wq   = (const float*)d_in[6];
    const float* bq   = (const float*)d_in[7];
    const float* gq   = (const float*)d_in[8];
    const float* Wa   = (const float*)d_in[9];
    const float* ba   = (const float*)d_in[10];
    const float* ga   = (const float*)d_in[11];

    float* out     = (float*)d_out;
    float* out_att = out;              // [B, H]
    float* out_w   = out + B_ * H_;    // [B, N, 1]

    const int smem_bytes = SMEM_FLOATS * sizeof(float);
    cudaFuncSetAttribute(main_kernel, cudaFuncAttributeMaxDynamicSharedMemorySize, smem_bytes);

    main_kernel<<<B_, THREADS, smem_bytes>>>(v, q, mask, Wv, bv, gv, Wq, bq, gq,
                                             Wa, ba, ga, out_att, out_w);
}

// round 7
// speedup vs baseline: 1.1716x; 1.1716x over previous
#include <cuda_runtime.h>
#include <cuda_fp16.h>
#include <math.h>
#include <stdint.h>

#define B_ 128
#define N_ 4096
#define H_ 128
#define P_ 128
#define NTILES 32
#define THREADS 256
#define NEGC (-10000.0f)

// fp16 tile row stride: 128 halves + 8 pad = 272 bytes (17*16B -> ldsm conflict-free)
#define HSTRIDE 272
// f32 scratch stride (Wq staging): 132 floats = 528 bytes
#define LDSF 132

// ---------------- smem layout (byte offsets) ----------------
#define BY_W     0                         // 128*272 = 34816 (fp16 scaled Wv)
#define BY_V0    34816                     // 34816 (fp16 V buf 0; f32 Wq scratch spans V0+V1 in setup)
#define BY_V1    69632                     // 34816
#define BY_LSM   104448                    // 4096 f32 logits = 16384
#define BY_QW    (BY_LSM + 16384)          // float2 qwas[128] = 1024
#define BY_WE    (BY_QW + 1024)            // 128 f32 = 512
#define BY_LGP   (BY_WE + 512)             // 2 x 256 f32 = 2048
#define BY_BC    (BY_LGP + 2048)           // 64
#define BY_RED   (BY_BC + 64)              // 16 f32 = 64
#define BY_SCL   (BY_RED + 64)             // 32
#define BY_QROW  (BY_SCL + 32)             // 128 f32 = 512
#define SMEM_BYTES (BY_QROW + 512)

// ---------------- helpers ----------------
__device__ __forceinline__ void mma_f16(float* d,
                                        uint32_t a0, uint32_t a1, uint32_t a2, uint32_t a3,
                                        uint32_t b0, uint32_t b1) {
    asm volatile(
        "mma.sync.aligned.m16n8k16.row.col.f32.f16.f16.f32 "
        "{%0,%1,%2,%3}, {%4,%5,%6,%7}, {%8,%9}, {%0,%1,%2,%3};"
        : "+f"(d[0]), "+f"(d[1]), "+f"(d[2]), "+f"(d[3])
        : "r"(a0), "r"(a1), "r"(a2), "r"(a3), "r"(b0), "r"(b1));
}

__device__ __forceinline__ void ldsm4(uint32_t* r, uint32_t addr) {
    asm volatile("ldmatrix.sync.aligned.m8n8.x4.shared.b16 {%0,%1,%2,%3}, [%4];"
                 : "=r"(r[0]), "=r"(r[1]), "=r"(r[2]), "=r"(r[3]) : "r"(addr));
}

#define BAR_SYNC(id, cnt)   asm volatile("bar.sync %0, %1;"   :: "r"(id), "r"(cnt) : "memory")
#define BAR_ARRIVE(id, cnt) asm volatile("bar.arrive %0, %1;" :: "r"(id), "r"(cnt) : "memory")
#define MEMBAR_CTA()        asm volatile("membar.cta;" ::: "memory")

// ---------------------------------------------------------------------------
// One CTA per batch row. 256 threads:
//   warps 0-3 (GEMM): 64x64 fp16 m16n8k16 mma blocks + relu-wa partials
//   warps 4-7 (helper): V fp32->fp16 staging, logits, online softmax, att.
// ---------------------------------------------------------------------------
__global__ void __launch_bounds__(THREADS, 1)
main_kernel(const float* __restrict__ v,
            const float* __restrict__ q,
            const float* __restrict__ mask,
            const float* __restrict__ Wv,
            const float* __restrict__ bv,
            const float* __restrict__ gv,
            const float* __restrict__ Wq,
            const float* __restrict__ bq,
            const float* __restrict__ gq,
            const float* __restrict__ Wa,
            const float* __restrict__ ba,
            const float* __restrict__ ga,
            float* __restrict__ out_att,
            float* __restrict__ out_w) {
    const int b    = blockIdx.x;
    const int tid  = threadIdx.x;
    const int warp = tid >> 5;
    const int lane = tid & 31;

    extern __shared__ char smc[];
    const uint32_t sb = (uint32_t)__cvta_generic_to_shared(smc);
    float*  lsm  = (float*)(smc + BY_LSM);
    float2* qwas = (float2*)(smc + BY_QW);
    float*  we   = (float*)(smc + BY_WE);
    float*  lgp  = (float*)(smc + BY_LGP);
    float*  bc   = (float*)(smc + BY_BC);
    float*  red  = (float*)(smc + BY_RED);
    float*  scl  = (float*)(smc + BY_SCL);
    float*  qrow = (float*)(smc + BY_QROW);
    float*  wqs  = (float*)(smc + BY_V0);     // f32 Wq scratch (setup only)

    const float* vsrc = v + (size_t)b * N_ * H_;
    const float4* vsrc4 = (const float4*)vsrc;

    // =================== setup (all 256 threads) ===================
    float s0 = 0.f;
    for (int i = tid; i < 4096; i += THREADS) {
        int row = i >> 5, c4 = i & 31;
        float4 w4 = __ldg((const float4*)Wq + i);
        *(float4*)(wqs + row * LDSF + c4 * 4) = w4;
        float4 a = __ldg((const float4*)Wv + i);
        s0 += a.x * a.x + a.y * a.y + a.z * a.z + a.w * a.w;
    }
    const float wa_own = (tid < P_) ? __ldg(&Wa[tid]) : 0.f;
    float s2 = wa_own * wa_own;
    if (tid < 32) ((float4*)qrow)[tid] = __ldg((const float4*)(q + b * H_) + tid);
    #pragma unroll
    for (int o = 16; o; o >>= 1) {
        s0 += __shfl_xor_sync(0xFFFFFFFFu, s0, o);
        s2 += __shfl_xor_sync(0xFFFFFFFFu, s2, o);
    }
    if (lane == 0) { red[warp] = s0; red[8 + warp] = s2; }
    __syncthreads();
    if (tid == 0) {
        float a = 0.f, c = 0.f;
        #pragma unroll
        for (int i = 0; i < 8; i++) { a += red[i]; c += red[8 + i]; }
        scl[0] = gv[0] / sqrtf(a);
        scl[2] = ga[0] / sqrtf(c);
        scl[3] = ba[0];
    }
    __syncthreads();
    const float sv = scl[0], sa = scl[2];

    // stage W as fp16 (scaled, RN-rounded): 2048 16B chunks
    for (int i = tid; i < 2048; i += THREADS) {
        int row = i >> 4, c8 = i & 15;
        float4 a = __ldg((const float4*)Wv + row * 32 + c8 * 2);
        float4 d = __ldg((const float4*)Wv + row * 32 + c8 * 2 + 1);
        half2 h0 = __floats2half2_rn(sv * a.x, sv * a.y);
        half2 h1 = __floats2half2_rn(sv * a.z, sv * a.w);
        half2 h2 = __floats2half2_rn(sv * d.x, sv * d.y);
        half2 h3 = __floats2half2_rn(sv * d.z, sv * d.w);
        uint4 u;
        u.x = *(uint32_t*)&h0; u.y = *(uint32_t*)&h1;
        u.z = *(uint32_t*)&h2; u.w = *(uint32_t*)&h3;
        *(uint4*)(smc + BY_W + row * HSTRIDE + c8 * 16) = u;
    }

    // qproj + Wq norm from f32 scratch (threads 0-127 own one row each)
    float dotv = 0.f, s1 = 0.f;
    if (tid < P_) {
        const float* wr = wqs + tid * LDSF;
        #pragma unroll 8
        for (int h = 0; h < H_; h++) {
            float w = wr[h];
            dotv += w * qrow[h];
            s1 += w * w;
        }
    }
    #pragma unroll
    for (int o = 16; o; o >>= 1) s1 += __shfl_xor_sync(0xFFFFFFFFu, s1, o);
    if (lane == 0 && warp < 4) red[warp] = s1;
    __syncthreads();
    if (tid == 0) scl[1] = gq[0] / sqrtf(red[0] + red[1] + red[2] + red[3]);
    __syncthreads();
    if (tid < P_) {
        float2 qv;
        qv.x = scl[1] * dotv + __ldg(&bq[tid]) + __ldg(&bv[tid]);
        qv.y = sa * wa_own;
        qwas[tid] = qv;
    }
    __syncthreads();   // Wq scratch (V0/V1 region) free from here
    const float ba0 = scl[3];

    // =================== split: GEMM group / helper group ===================
    if (warp < 4) {
        // ---------------- GEMM group: warp owns 64 rows x 64 cols ----------------
        const int t4 = lane & 3;
        const int mi = warp & 1;
        const int ni = warp >> 1;
        const int j  = lane >> 3;
        uint32_t aoff[4], boff[4];
        #pragma unroll
        for (int m = 0; m < 4; m++) {
            int row = mi * 64 + m * 16 + ((j & 1) << 3) + (lane & 7);
            aoff[m] = (uint32_t)(row * HSTRIDE + ((j >> 1) << 4));
        }
        #pragma unroll
        for (int p = 0; p < 4; p++) {
            int row = ni * 64 + p * 16 + ((j >> 1) << 3) + (lane & 7);
            boff[p] = (uint32_t)(BY_W + row * HSTRIDE + ((j & 1) << 4));
        }

        float4 qw[8];
        #pragma unroll
        for (int n = 0; n < 8; n++)
            qw[n] = *(const float4*)&qwas[ni * 64 + n * 8 + 2 * t4];

        for (int t = 0; t < NTILES; t++) {
            BAR_SYNC(1, THREADS);                   // V(t) staged in buf(t&1)
            const uint32_t vb = sb + ((t & 1) ? BY_V1 : BY_V0);

            float acc[4][8][4];
            #pragma unroll
            for (int m = 0; m < 4; m++)
                #pragma unroll
                for (int n = 0; n < 8; n++)
                    #pragma unroll
                    for (int x = 0; x < 4; x++) acc[m][n][x] = 0.f;

            #pragma unroll
            for (int k = 0; k < 8; k++) {           // k16 per step
                uint32_t a[4][4], bb[4][4];
                #pragma unroll
                for (int m = 0; m < 4; m++) ldsm4(a[m], vb + aoff[m] + 32 * k);
                #pragma unroll
                for (int p = 0; p < 4; p++) ldsm4(bb[p], sb + boff[p] + 32 * k);
                #pragma unroll
                for (int m = 0; m < 4; m++)
                    #pragma unroll
                    for (int n = 0; n < 8; n++)
                        mma_f16(acc[m][n], a[m][0], a[m][1], a[m][2], a[m][3],
                                bb[n >> 1][(n & 1) * 2], bb[n >> 1][(n & 1) * 2 + 1]);
            }

            // relu + wa dot -> row partials into lgp[t&1]
            float* lgpb = lgp + (t & 1) * 256;
            #pragma unroll
            for (int m = 0; m < 4; m++) {
                float pl0 = 0.f, pl1 = 0.f;
                #pragma unroll
                for (int n = 0; n < 8; n++) {
                    pl0 += fmaxf(acc[m][n][0] + qw[n].x, 0.f) * qw[n].y
                         + fmaxf(acc[m][n][1] + qw[n].z, 0.f) * qw[n].w;
                    pl1 += fmaxf(acc[m][n][2] + qw[n].x, 0.f) * qw[n].y
                         + fmaxf(acc[m][n][3] + qw[n].z, 0.f) * qw[n].w;
                }
                pl0 += __shfl_xor_sync(0xFFFFFFFFu, pl0, 1);
                pl0 += __shfl_xor_sync(0xFFFFFFFFu, pl0, 2);
                pl1 += __shfl_xor_sync(0xFFFFFFFFu, pl1, 1);
                pl1 += __shfl_xor_sync(0xFFFFFFFFu, pl1, 2);
                if (t4 == 0) {
                    const int gg = lane >> 2;
                    const int r0 = mi * 64 + m * 16 + gg;
                    lgpb[r0 * 2 + ni]       = pl0;
                    lgpb[(r0 + 8) * 2 + ni] = pl1;
                }
            }
            MEMBAR_CTA();
            BAR_ARRIVE(2, THREADS);                 // lgp(t) ready
        }
    } else {
        // ---------------- helper group ----------------
        const int ht = tid - 128;     // 0..127
        const int hw = warp - 4;      // 0..3
        float4 vr[32];

        // V(0): LDG -> cvt -> STS buf0
        #pragma unroll
        for (int jj = 0; jj < 32; jj++) vr[jj] = __ldg(vsrc4 + jj * 128 + ht);
        #pragma unroll
        for (int jj = 0; jj < 32; jj++) {
            int idx = jj * 128 + ht, row = idx >> 5, c4 = idx & 31;
            half2 h0 = __floats2half2_rn(vr[jj].x, vr[jj].y);
            half2 h1 = __floats2half2_rn(vr[jj].z, vr[jj].w);
            uint2 u; u.x = *(uint32_t*)&h0; u.y = *(uint32_t*)&h1;
            *(uint2*)(smc + BY_V0 + row * HSTRIDE + c4 * 8) = u;
        }
        MEMBAR_CTA();
        BAR_ARRIVE(1, THREADS);                      // release GEMM(0)
        // V(1) -> regs
        #pragma unroll
        for (int jj = 0; jj < 32; jj++) vr[jj] = __ldg(vsrc4 + 4096 + jj * 128 + ht);

        float M = -INFINITY, S = 0.f, attp = 0.f;

        for (int t = 0; t < NTILES; t++) {
            // stage V(t+1) into buf((t+1)&1), release GEMM(t+1)
            if (t + 1 < NTILES) {
                const int bufoff = ((t + 1) & 1) ? BY_V1 : BY_V0;
                #pragma unroll
                for (int jj = 0; jj < 32; jj++) {
                    int idx = jj * 128 + ht, row = idx >> 5, c4 = idx & 31;
                    half2 h0 = __floats2half2_rn(vr[jj].x, vr[jj].y);
                    half2 h1 = __floats2half2_rn(vr[jj].z, vr[jj].w);
                    uint2 u; u.x = *(uint32_t*)&h0; u.y = *(uint32_t*)&h1;
                    *(uint2*)(smc + bufoff + row * HSTRIDE + c4 * 8) = u;
                }
                MEMBAR_CTA();
                BAR_ARRIVE(1, THREADS);
            }
            const float mkv = __ldg(&mask[(size_t)b * N_ + t * 128 + ht]);
            BAR_SYNC(2, THREADS);                    // lgp(t) ready

            // combine partials + mask -> logit
            const float* lgpb = lgp + (t & 1) * 256;
            float l = lgpb[ht * 2] + lgpb[ht * 2 + 1] + ba0 + (1.f - mkv) * NEGC;
            lsm[t * 128 + ht] = l;

            float x = l;
            #pragma unroll
            for (int o = 16; o; o >>= 1) x = fmaxf(x, __shfl_xor_sync(0xFFFFFFFFu, x, o));
            if (lane == 0) bc[hw] = x;
            BAR_SYNC(3, 128);
            float Mn = fmaxf(M, fmaxf(fmaxf(bc[0], bc[1]), fmaxf(bc[2], bc[3])));
            float r  = __expf(M - Mn);
            float e  = __expf(l - Mn);
            we[ht] = e;
            #pragma unroll
            for (int o = 16; o; o >>= 1) e += __shfl_xor_sync(0xFFFFFFFFu, e, o);
            if (lane == 0) bc[8 + hw] = e;
            BAR_SYNC(3, 128);
            S = S * r + (bc[8] + bc[9] + bc[10] + bc[11]);
            M = Mn;

            // att update from fp16 V(t)
            const __half* Vh = (const __half*)(smc + ((t & 1) ? BY_V1 : BY_V0)) + ht;
            float a0 = 0.f, a1 = 0.f, a2 = 0.f, a3 = 0.f;
            #pragma unroll 8
            for (int row = 0; row < 128; row += 4) {
                a0 += we[row]     * __half2float(Vh[row * 136]);
                a1 += we[row + 1] * __half2float(Vh[(row + 1) * 136]);
                a2 += we[row + 2] * __half2float(Vh[(row + 2) * 136]);
                a3 += we[row + 3] * __half2float(Vh[(row + 3) * 136]);
            }
            attp = attp * r + ((a0 + a1) + (a2 + a3));
            BAR_SYNC(3, 128);                        // att reads of buf(t&1) done

            // LDG V(t+2) -> regs
            if (t + 2 < NTILES) {
                const float4* src4 = vsrc4 + (size_t)(t + 2) * 4096;
                #pragma unroll
                for (int jj = 0; jj < 32; jj++) vr[jj] = __ldg(src4 + jj * 128 + ht);
            }
        }

        if (ht == 0) { red[0] = M; red[1] = 1.f / S; }
        out_att[b * H_ + ht] = attp / S;
    }

    // =================== finals (all 256) ===================
    __syncthreads();
    const float Mf = red[0], invS = red[1];
    #pragma unroll 4
    for (int n = tid; n < N_; n += THREADS) {
        out_w[(size_t)b * N_ + n] = __expf(lsm[n] - Mf) * invS;
    }
}

// ---------------------------------------------------------------------------
extern "C" void kernel_launch(void* const* d_in, const int* in_sizes, int n_in,
                              void* d_out, int out_size) {
    const float* v    = (const float*)d_in[0];
    const float* q    = (const float*)d_in[1];
    const float* mask = (const float*)d_in[2];
    const float* Wv   = (const float*)d_in[3];
    const float* bv   = (const float*)d_in[4];
    const float* gv   = (const float*)d_in[5];
    const float* Wq   = (const float*)d_in[6];
    const float* bq   = (const float*)d_in[7];
    const float* gq   = (const float*)d_in[8];
    const float* Wa   = (const float*)d_in[9];
    const float* ba   = (const float*)d_in[10];
    const float* ga   = (const float*)d_in[11];

    float* out     = (float*)d_out;
    float* out_att = out;              // [B, H]
    float* out_w   = out + B_ * H_;    // [B, N, 1]

    cudaFuncSetAttribute(main_kernel, cudaFuncAttributeMaxDynamicSharedMemorySize, SMEM_BYTES);

    main_kernel<<<B_, THREADS, SMEM_BYTES>>>(v, q, mask, Wv, bv, gv, Wq, bq, gq,
                                             Wa, ba, ga, out_att, out_w);
}